// round 3
// baseline (speedup 1.0000x reference)
#include <cuda_runtime.h>
#include <math.h>

#define H 1024
#define E 512
#define A 512
#define L 512
#define V 50257
#define NSLICE 16

// ---------------- scratch (device globals) ----------------------------------
__device__ __align__(16) float g_scores[L];
__device__ __align__(16) float g_part[NSLICE * H];
__device__ __align__(16) float g_x[H];
__device__ __align__(16) float g_gates[4 * H];
__device__ __align__(16) float g_h[H];

__device__ __forceinline__ float warp_sum(float v) {
#pragma unroll
    for (int o = 16; o > 0; o >>= 1) v += __shfl_down_sync(0xffffffffu, v, o);
    return v;
}

// ---------------- K1: attn scores (512 x 1536), 2 warps per row -------------
__global__ __launch_bounds__(256) void k_attn_score(
        const int* __restrict__ word, const float* __restrict__ emb,
        const float* __restrict__ h0, const float* __restrict__ attn_W,
        const float* __restrict__ attn_b) {
    __shared__ float sc[E + H];
    __shared__ float sred[8];
    int t = threadIdx.x, lane = t & 31, w = t >> 5;
    long wrow = (long)word[0] * E;
#pragma unroll
    for (int i = t; i < E + H; i += 256)
        sc[i] = (i < E) ? emb[wrow + i] : h0[i - E];
    __syncthreads();
    int row  = blockIdx.x * 4 + (w >> 1);
    int half = w & 1;                               // 768 floats = 192 float4
    const float4* wr = reinterpret_cast<const float4*>(attn_W)
                       + (size_t)row * (1536 / 4) + half * 192;
    const float4* c4 = reinterpret_cast<const float4*>(sc) + half * 192;
    float s = 0.f;
#pragma unroll
    for (int i = 0; i < 6; i++) {
        float4 a = __ldcs(&wr[lane + 32 * i]);
        float4 b = c4[lane + 32 * i];
        s += a.x * b.x + a.y * b.y + a.z * b.z + a.w * b.w;
    }
    s = warp_sum(s);
    if (lane == 0) sred[w] = s;
    __syncthreads();
    if (t < 4) {
        int r = blockIdx.x * 4 + t;
        g_scores[r] = sred[2 * t] + sred[2 * t + 1] + attn_b[r];
    }
}

// ---------------- K2: fused softmax + attn apply partials -------------------
// grid (2 col-halves, NSLICE slices), block 128. Softmax recomputed per block
// (identical deterministic reduction); block (0,0) writes the weights output.
__global__ __launch_bounds__(128) void k_attn_apply(
        const float* __restrict__ enc, float* __restrict__ d_attn_out) {
    __shared__ float sred[4];
    __shared__ float sw[L];
    __shared__ float sbc;
    int t = threadIdx.x, lane = t & 31, wid = t >> 5;

    float v[4];
#pragma unroll
    for (int k = 0; k < 4; k++) v[k] = g_scores[t + 128 * k];
    float m = fmaxf(fmaxf(v[0], v[1]), fmaxf(v[2], v[3]));
#pragma unroll
    for (int o = 16; o > 0; o >>= 1) m = fmaxf(m, __shfl_xor_sync(0xffffffffu, m, o));
    if (lane == 0) sred[wid] = m;
    __syncthreads();
    if (t == 0) sbc = fmaxf(fmaxf(sred[0], sred[1]), fmaxf(sred[2], sred[3]));
    __syncthreads();
    float bmax = sbc;
    float e[4];
    float su = 0.f;
#pragma unroll
    for (int k = 0; k < 4; k++) { e[k] = expf(v[k] - bmax); su += e[k]; }
#pragma unroll
    for (int o = 16; o > 0; o >>= 1) su += __shfl_xor_sync(0xffffffffu, su, o);
    __syncthreads();
    if (lane == 0) sred[wid] = su;
    __syncthreads();
    if (t == 0) sbc = sred[0] + sred[1] + sred[2] + sred[3];
    __syncthreads();
    float inv = 1.0f / sbc;
#pragma unroll
    for (int k = 0; k < 4; k++) {
        float wk = e[k] * inv;
        sw[t + 128 * k] = wk;
        if (blockIdx.x == 0 && blockIdx.y == 0) d_attn_out[t + 128 * k] = wk;
    }
    __syncthreads();

    // this block: 32 enc rows x 512 cols (128 float4)
    int l0 = blockIdx.y * (L / NSLICE);
    int c0 = blockIdx.x * 128;                     // float4 col offset
    const float4* e4 = reinterpret_cast<const float4*>(enc);
    float4 acc = make_float4(0.f, 0.f, 0.f, 0.f);
#pragma unroll
    for (int l = 0; l < L / NSLICE; l++) {
        float wk = sw[l0 + l];
        float4 x = __ldcs(&e4[(size_t)(l0 + l) * (H / 4) + c0 + t]);
        acc.x += wk * x.x; acc.y += wk * x.y; acc.z += wk * x.z; acc.w += wk * x.w;
    }
    reinterpret_cast<float4*>(g_part)[blockIdx.y * (H / 4) + c0 + t] = acc;
}

// ---------------- K3: combine + relu (1024 x 2048), 2 warps per row ---------
__global__ __launch_bounds__(256) void k_comb(
        const int* __restrict__ word, const float* __restrict__ emb,
        const float* __restrict__ av, const float* __restrict__ comb_W,
        const float* __restrict__ comb_b) {
    __shared__ float sc[E + H + A];
    __shared__ float sred[8];
    int t = threadIdx.x, lane = t & 31, w = t >> 5;
    long wrow = (long)word[0] * E;
#pragma unroll
    for (int i = t; i < E + H + A; i += 256) {
        float v;
        if (i < E) v = emb[wrow + i];
        else if (i < E + H) {
            int j = i - E;
            float s = 0.f;
#pragma unroll
            for (int p = 0; p < NSLICE; p++) s += g_part[p * H + j];
            v = s;
        } else v = av[i - (E + H)];
        sc[i] = v;
    }
    __syncthreads();
    int row  = blockIdx.x * 4 + (w >> 1);
    int half = w & 1;                               // 1024 floats = 256 float4
    const float4* wr = reinterpret_cast<const float4*>(comb_W)
                       + (size_t)row * (2048 / 4) + half * 256;
    const float4* c4 = reinterpret_cast<const float4*>(sc) + half * 256;
    float s = 0.f;
#pragma unroll
    for (int i = 0; i < 8; i++) {
        float4 a = __ldcs(&wr[lane + 32 * i]);
        float4 b = c4[lane + 32 * i];
        s += a.x * b.x + a.y * b.y + a.z * b.z + a.w * b.w;
    }
    s = warp_sum(s);
    if (lane == 0) sred[w] = s;
    __syncthreads();
    if (t < 4) {
        int r = blockIdx.x * 4 + t;
        g_x[r] = fmaxf(sred[2 * t] + sred[2 * t + 1] + comb_b[r], 0.f);
    }
}

// ---------------- K4: LSTM gates, warp per (row, matrix) --------------------
__global__ __launch_bounds__(256) void k_gates(
        const float* __restrict__ W_ih, const float* __restrict__ W_hh,
        const float* __restrict__ b_ih, const float* __restrict__ b_hh,
        const float* __restrict__ h0) {
    __shared__ float4 svec[2][H / 4];   // [0]=x, [1]=h
    __shared__ float sred[8];
    int t = threadIdx.x, lane = t & 31, w = t >> 5;
    svec[0][t] = reinterpret_cast<const float4*>(g_x)[t];
    svec[1][t] = reinterpret_cast<const float4*>(h0)[t];
    __syncthreads();
    int row = blockIdx.x * 4 + (w >> 1);
    int mat = w & 1;
    const float* W = mat ? W_hh : W_ih;
    const float4* wr = reinterpret_cast<const float4*>(W) + (size_t)row * (H / 4);
    const float4* c4 = svec[mat];
    float s = 0.f;
#pragma unroll
    for (int i = 0; i < 8; i++) {
        float4 a = __ldcs(&wr[lane + 32 * i]);
        float4 b = c4[lane + 32 * i];
        s += a.x * b.x + a.y * b.y + a.z * b.z + a.w * b.w;
    }
    s = warp_sum(s);
    if (lane == 0) sred[w] = s;
    __syncthreads();
    if (t < 4) {
        int r = blockIdx.x * 4 + t;
        g_gates[r] = sred[2 * t] + sred[2 * t + 1] + b_ih[r] + b_hh[r];
    }
}

// ---------------- K5: LSTM pointwise ----------------------------------------
__global__ __launch_bounds__(1024) void k_lstm(
        const float* __restrict__ c0, float* __restrict__ d_h,
        float* __restrict__ d_c) {
    int k = threadIdx.x;
    float gi = g_gates[k];
    float gf = g_gates[H + k];
    float gg = g_gates[2 * H + k];
    float go = g_gates[3 * H + k];
    float si = 1.f / (1.f + expf(-gi));
    float sf = 1.f / (1.f + expf(-gf));
    float so = 1.f / (1.f + expf(-go));
    float cn = sf * c0[k] + si * tanhf(gg);
    float hn = so * tanhf(cn);
    g_h[k] = hn;
    d_h[k] = hn;
    d_c[k] = cn;
}

// ---------------- K6: logits (50257 x 1024), 2 rows per warp ----------------
__global__ __launch_bounds__(256) void k_logits(
        const float* __restrict__ out_W, const float* __restrict__ out_b,
        float* __restrict__ logits) {
    __shared__ float4 sh[H / 4];
    int t = threadIdx.x, lane = t & 31, w = t >> 5;
    sh[t] = reinterpret_cast<const float4*>(g_h)[t];
    __syncthreads();
    int r0 = blockIdx.x * 16 + 2 * w;
    int r1 = r0 + 1;
    int r0c = r0 < V ? r0 : V - 1;
    int r1c = r1 < V ? r1 : V - 1;
    const float4* wr0 = reinterpret_cast<const float4*>(out_W) + (size_t)r0c * (H / 4);
    const float4* wr1 = reinterpret_cast<const float4*>(out_W) + (size_t)r1c * (H / 4);
    float s0 = 0.f, s1 = 0.f;
#pragma unroll
    for (int i = 0; i < 8; i++) {
        float4 a = __ldcs(&wr0[lane + 32 * i]);
        float4 b = __ldcs(&wr1[lane + 32 * i]);
        float4 h = sh[lane + 32 * i];
        s0 += a.x * h.x + a.y * h.y + a.z * h.z + a.w * h.w;
        s1 += b.x * h.x + b.y * h.y + b.z * h.z + b.w * h.w;
    }
    s0 = warp_sum(s0);
    s1 = warp_sum(s1);
    if (lane == 0) {
        if (r0 < V) logits[r0] = s0 + out_b[r0];
        if (r1 < V) logits[r1] = s1 + out_b[r1];
    }
}

// ---------------- launch ----------------------------------------------------
extern "C" void kernel_launch(void* const* d_in, const int* in_sizes, int n_in,
                              void* d_out, int out_size) {
    (void)out_size;
    const int* word = (const int*)d_in[0];
    int k = (n_in >= 2 && in_sizes[1] == 1) ? 2 : 1;
    const float* av_emb  = (const float*)d_in[k + 0];
    const float* h0      = (const float*)d_in[k + 1];
    const float* c0      = (const float*)d_in[k + 2];
    const float* enc_out = (const float*)d_in[k + 3];
    const float* emb     = (const float*)d_in[k + 4];
    const float* attn_W  = (const float*)d_in[k + 5];
    const float* attn_b  = (const float*)d_in[k + 6];
    const float* comb_W  = (const float*)d_in[k + 7];
    const float* comb_b  = (const float*)d_in[k + 8];
    const float* W_ih    = (const float*)d_in[k + 9];
    const float* W_hh    = (const float*)d_in[k + 10];
    const float* b_ih    = (const float*)d_in[k + 11];
    const float* b_hh    = (const float*)d_in[k + 12];
    const float* out_W   = (const float*)d_in[k + 13];
    const float* out_b   = (const float*)d_in[k + 14];

    float* out = (float*)d_out;
    float* o_logits = out;              // [V]
    float* o_h      = out + V;          // [H]
    float* o_c      = out + V + H;      // [H]
    float* o_attn   = out + V + 2 * H;  // [L]

    k_attn_score<<<L / 4, 256>>>(word, emb, h0, attn_W, attn_b);
    k_attn_apply<<<dim3(2, NSLICE), 128>>>(enc_out, o_attn);
    k_comb<<<H / 4, 256>>>(word, emb, av_emb, comb_W, comb_b);
    k_gates<<<(4 * H) / 4, 256>>>(W_ih, W_hh, b_ih, b_hh, h0);
    k_lstm<<<1, 1024>>>(c0, o_h, o_c);
    k_logits<<<(V + 15) / 16, 256>>>(out_W, out_b, o_logits);
}